// round 2
// baseline (speedup 1.0000x reference)
#include <cuda_runtime.h>
#include <cuda_bf16.h>
#include <stdint.h>

typedef unsigned long long ull;

#define N_ROWS 32768
#define K_CODES 8192
#define D_DIM 256
#define SX 132                    // smem row stride (floats), 16B-aligned (132*4=528)
#define SMEM_BYTES ((256*SX + 64*SX) * 4)   // xs[256][132] + ws[64][132] = 168960 B

__device__ float  g_wsq[K_CODES];
__device__ float  g_xsq[N_ROWS];
__device__ int    g_idx[N_ROWS];
__device__ double g_part[4096];

__device__ __forceinline__ ull fma2(ull a, ull b, ull c) {
    ull d;
    asm("fma.rn.f32x2 %0, %1, %2, %3;" : "=l"(d) : "l"(a), "l"(b), "l"(c));
    return d;
}
__device__ __forceinline__ ull pack2(float a, float b) {
    ull r;
    asm("mov.b64 %0, {%1, %2};" : "=l"(r) : "f"(a), "f"(b));
    return r;
}
__device__ __forceinline__ void unpack2(ull v, float& lo, float& hi) {
    asm("mov.b64 {%0, %1}, %2;" : "=f"(lo), "=f"(hi) : "l"(v));
}

// sum of squares per row of [nrows, 256]; order-insensitive for argmin (see theory)
__global__ __launch_bounds__(256)
void rowsq_kernel(const float* __restrict__ src, int nrows, int which) {
    int row = blockIdx.x * 256 + threadIdx.x;
    if (row >= nrows) return;
    const float4* p = (const float4*)(src + (size_t)row * D_DIM);
    float s0 = 0.f, s1 = 0.f, s2 = 0.f, s3 = 0.f;
    #pragma unroll 8
    for (int c = 0; c < D_DIM / 4; ++c) {
        float4 v = __ldg(p + c);
        s0 = __fmaf_rn(v.x, v.x, s0);
        s1 = __fmaf_rn(v.y, v.y, s1);
        s2 = __fmaf_rn(v.z, v.z, s2);
        s3 = __fmaf_rn(v.w, v.w, s3);
    }
    float r = __fadd_rn(__fadd_rn(s0, s1), __fadd_rn(s2, s3));
    if (which == 0) g_wsq[row] = r; else g_xsq[row] = r;
}

// Fused dist2 argmin over K. Block tile 128 rows x 128 cols per iteration,
// 64 col-tiles. f32x2 packed FMA, sequential-k accumulation per lane.
__global__ __launch_bounds__(256, 1)
void vq_argmin_kernel(const float* __restrict__ x, const float* __restrict__ w,
                      float* __restrict__ idx_out)
{
    extern __shared__ float sm[];
    float* xs = sm;              // [256 d][132] rows-contiguous
    float* ws = sm + 256 * SX;   // [64 d][132] cols-contiguous

    const int tid = threadIdx.x;
    const int tx = tid & 15;     // col-group 0..15
    const int ty = tid >> 4;     // row-group 0..15
    const int r0 = blockIdx.x * 128;

    // load x tile transposed: xs[d][r]
    #pragma unroll
    for (int i = 0; i < 32; ++i) {
        int e = i * 256 + tid;
        int row = e >> 6, q = e & 63;
        float4 v = __ldg((const float4*)(x + (size_t)(r0 + row) * D_DIM) + q);
        int d = q * 4;
        xs[(d + 0) * SX + row] = v.x;
        xs[(d + 1) * SX + row] = v.y;
        xs[(d + 2) * SX + row] = v.z;
        xs[(d + 3) * SX + row] = v.w;
    }

    float xsqr[8], bestv[8];
    int besti[8];
    #pragma unroll
    for (int r = 0; r < 8; ++r) {
        xsqr[r] = g_xsq[r0 + ty * 8 + r];
        bestv[r] = 3.4e38f;
        besti[r] = 0;
    }
    __syncthreads();

    for (int t = 0; t < K_CODES / 128; ++t) {
        ull acc[8][4];
        #pragma unroll
        for (int r = 0; r < 8; ++r)
            #pragma unroll
            for (int c = 0; c < 4; ++c) acc[r][c] = 0ull;

        for (int ch = 0; ch < 4; ++ch) {
            // load W chunk transposed: ws[d][c] for cols t*128.., d = ch*64..
            #pragma unroll
            for (int i = 0; i < 8; ++i) {
                int e = i * 256 + tid;
                int c = e >> 4, q = e & 15;
                int d = q * 4;
                float4 v = __ldg((const float4*)(w + (size_t)(t * 128 + c) * D_DIM
                                                 + ch * 64) + q);
                ws[(d + 0) * SX + c] = v.x;
                ws[(d + 1) * SX + c] = v.y;
                ws[(d + 2) * SX + c] = v.z;
                ws[(d + 3) * SX + c] = v.w;
            }
            __syncthreads();

            const float* xbase = xs + (ch * 64) * SX + ty * 8;
            const float* wbase = ws + tx * 8;
            #pragma unroll 8
            for (int d = 0; d < 64; ++d) {
                float4 xA = *(const float4*)(xbase + d * SX);
                float4 xB = *(const float4*)(xbase + d * SX + 4);
                ulonglong2 wA = *(const ulonglong2*)(wbase + d * SX);
                ulonglong2 wB = *(const ulonglong2*)(wbase + d * SX + 4);
                float xr[8] = {xA.x, xA.y, xA.z, xA.w, xB.x, xB.y, xB.z, xB.w};
                ull wp[4] = {wA.x, wA.y, wB.x, wB.y};
                #pragma unroll
                for (int r = 0; r < 8; ++r) {
                    ull px = pack2(xr[r], xr[r]);
                    #pragma unroll
                    for (int c = 0; c < 4; ++c)
                        acc[r][c] = fma2(px, wp[c], acc[r][c]);
                }
            }
            __syncthreads();  // before next chunk overwrites ws
        }

        // epilogue: replicate ref's fp32 op sequence; strict-less keeps first index
        int cbase = t * 128 + tx * 8;
        float wsqv[8];
        #pragma unroll
        for (int j = 0; j < 8; ++j) wsqv[j] = __ldg(&g_wsq[cbase + j]);
        #pragma unroll
        for (int r = 0; r < 8; ++r) {
            #pragma unroll
            for (int c = 0; c < 4; ++c) {
                float glo, ghi;
                unpack2(acc[r][c], glo, ghi);
                float d1 = __fsub_rn(xsqr[r], __fmul_rn(2.0f, glo));
                float dv = __fadd_rn(d1, wsqv[2 * c]);
                if (dv < bestv[r]) { bestv[r] = dv; besti[r] = cbase + 2 * c; }
                d1 = __fsub_rn(xsqr[r], __fmul_rn(2.0f, ghi));
                dv = __fadd_rn(d1, wsqv[2 * c + 1]);
                if (dv < bestv[r]) { bestv[r] = dv; besti[r] = cbase + 2 * c + 1; }
            }
        }
    }

    // reduce across the 16 tx lanes (within half-warp), lexicographic (val, idx)
    #pragma unroll
    for (int r = 0; r < 8; ++r) {
        float v = bestv[r];
        int bi = besti[r];
        #pragma unroll
        for (int m = 8; m > 0; m >>= 1) {
            float vo = __shfl_xor_sync(0xffffffffu, v, m);
            int io = __shfl_xor_sync(0xffffffffu, bi, m);
            if (vo < v || (vo == v && io < bi)) { v = vo; bi = io; }
        }
        if (tx == 0) {
            int row = r0 + ty * 8 + r;
            g_idx[row] = bi;
            if (idx_out) idx_out[row] = (float)bi;
        }
    }
}

// gather codewords, write straight-through output, accumulate loss partials
__global__ __launch_bounds__(256)
void loss_gather_kernel(const float* __restrict__ x, const float* __restrict__ w,
                        float* __restrict__ qst)
{
    __shared__ double sred[256];
    int tid = threadIdx.x;
    double s = 0.0;
    size_t base = (size_t)blockIdx.x * 2048;
    #pragma unroll
    for (int i = 0; i < 2; ++i) {
        size_t e = base + (size_t)tid * 4 + (size_t)i * 1024;
        int row = (int)(e >> 8);
        int d = (int)(e & 255);
        int idx = g_idx[row];
        float4 xv = *(const float4*)(x + e);
        float4 qv = __ldg((const float4*)(w + (size_t)idx * D_DIM + d));
        float4 o;
        o.x = __fadd_rn(xv.x, __fsub_rn(qv.x, xv.x));
        o.y = __fadd_rn(xv.y, __fsub_rn(qv.y, xv.y));
        o.z = __fadd_rn(xv.z, __fsub_rn(qv.z, xv.z));
        o.w = __fadd_rn(xv.w, __fsub_rn(qv.w, xv.w));
        *(float4*)(qst + e) = o;
        float dx;
        dx = __fsub_rn(xv.x, qv.x); s += (double)__fmul_rn(dx, dx);
        dx = __fsub_rn(xv.y, qv.y); s += (double)__fmul_rn(dx, dx);
        dx = __fsub_rn(xv.z, qv.z); s += (double)__fmul_rn(dx, dx);
        dx = __fsub_rn(xv.w, qv.w); s += (double)__fmul_rn(dx, dx);
    }
    sred[tid] = s;
    __syncthreads();
    for (int st = 128; st > 0; st >>= 1) {
        if (tid < st) sred[tid] += sred[tid + st];
        __syncthreads();
    }
    if (tid == 0) g_part[blockIdx.x] = sred[0];
}

__global__ __launch_bounds__(256)
void finalize_kernel(float* __restrict__ sc)
{
    __shared__ double sred[256];
    int tid = threadIdx.x;
    double s = 0.0;
    for (int j = tid; j < 4096; j += 256) s += g_part[j];
    sred[tid] = s;
    __syncthreads();
    for (int st = 128; st > 0; st >>= 1) {
        if (tid < st) sred[tid] += sred[tid + st];
        __syncthreads();
    }
    if (tid == 0 && sc) {
        double mean = sred[0] / (double)((size_t)N_ROWS * D_DIM);
        float M = (float)mean;
        float commit = __fmul_rn(M, 0.25f);
        sc[0] = commit;                 // commitment_loss
        sc[1] = M;                      // codebook_loss
        sc[2] = __fadd_rn(commit, M);   // total
    }
}

extern "C" void kernel_launch(void* const* d_in, const int* in_sizes, int n_in,
                              void* d_out, int out_size)
{
    const float* x = (const float*)d_in[0];
    const float* w = (const float*)d_in[1];
    // defensive: identify x (N*D) vs weight (K*D) by element count
    if (n_in >= 2 && in_sizes[0] == K_CODES * D_DIM && in_sizes[1] == N_ROWS * D_DIM) {
        const float* t = x; x = w; w = t;
    }

    float* out = (float*)d_out;
    const int ND = N_ROWS * D_DIM;
    float* qst = out;
    float* idxo = (out_size >= ND + N_ROWS) ? out + ND : nullptr;
    float* sc = (out_size >= ND + N_ROWS + 3) ? out + ND + N_ROWS : nullptr;

    static int smem_set = 0;
    if (!smem_set) {
        cudaFuncSetAttribute(vq_argmin_kernel,
                             cudaFuncAttributeMaxDynamicSharedMemorySize, SMEM_BYTES);
        smem_set = 1;
    }

    rowsq_kernel<<<K_CODES / 256, 256>>>(w, K_CODES, 0);
    rowsq_kernel<<<N_ROWS / 256, 256>>>(x, N_ROWS, 1);
    vq_argmin_kernel<<<N_ROWS / 128, 256, SMEM_BYTES>>>(x, w, idxo);
    loss_gather_kernel<<<4096, 256>>>(x, w, qst);
    finalize_kernel<<<1, 256>>>(sc);
}

// round 3
// speedup vs baseline: 1.0009x; 1.0009x over previous
#include <cuda_runtime.h>
#include <cuda_bf16.h>
#include <stdint.h>

typedef unsigned long long ull;

#define N_ROWS 32768
#define K_CODES 8192
#define D_DIM 256
#define SX 132                    // smem row stride (floats), 16B-aligned (132*4=528)
#define SMEM_BYTES ((256*SX + 64*SX) * 4)   // xs[256][132] + ws[64][132] = 168960 B

__device__ float  g_wsq[K_CODES];
__device__ float  g_xsq[N_ROWS];
__device__ int    g_idx[N_ROWS];
__device__ double g_part[4096];

__device__ __forceinline__ ull fma2(ull a, ull b, ull c) {
    ull d;
    asm("fma.rn.f32x2 %0, %1, %2, %3;" : "=l"(d) : "l"(a), "l"(b), "l"(c));
    return d;
}
__device__ __forceinline__ ull pack2(float a, float b) {
    ull r;
    asm("mov.b64 %0, {%1, %2};" : "=l"(r) : "f"(a), "f"(b));
    return r;
}
__device__ __forceinline__ void unpack2(ull v, float& lo, float& hi) {
    asm("mov.b64 {%0, %1}, %2;" : "=f"(lo), "=f"(hi) : "l"(v));
}

// sum of squares per row of [nrows, 256]; order-insensitive for argmin (see theory)
__global__ __launch_bounds__(256)
void rowsq_kernel(const float* __restrict__ src, int nrows, int which) {
    int row = blockIdx.x * 256 + threadIdx.x;
    if (row >= nrows) return;
    const float4* p = (const float4*)(src + (size_t)row * D_DIM);
    float s0 = 0.f, s1 = 0.f, s2 = 0.f, s3 = 0.f;
    #pragma unroll 8
    for (int c = 0; c < D_DIM / 4; ++c) {
        float4 v = __ldg(p + c);
        s0 = __fmaf_rn(v.x, v.x, s0);
        s1 = __fmaf_rn(v.y, v.y, s1);
        s2 = __fmaf_rn(v.z, v.z, s2);
        s3 = __fmaf_rn(v.w, v.w, s3);
    }
    float r = __fadd_rn(__fadd_rn(s0, s1), __fadd_rn(s2, s3));
    if (which == 0) g_wsq[row] = r; else g_xsq[row] = r;
}

// Fused dist2 argmin over K. Block tile 128 rows x 128 cols per iteration,
// 64 col-tiles. f32x2 packed FMA, sequential-k accumulation per lane.
__global__ __launch_bounds__(256, 1)
void vq_argmin_kernel(const float* __restrict__ x, const float* __restrict__ w,
                      float* __restrict__ idx_out)
{
    extern __shared__ float sm[];
    float* xs = sm;              // [256 d][132] rows-contiguous
    float* ws = sm + 256 * SX;   // [64 d][132] cols-contiguous

    const int tid = threadIdx.x;
    const int tx = tid & 15;     // col-group 0..15
    const int ty = tid >> 4;     // row-group 0..15
    const int r0 = blockIdx.x * 128;

    // load x tile transposed: xs[d][r]
    #pragma unroll
    for (int i = 0; i < 32; ++i) {
        int e = i * 256 + tid;
        int row = e >> 6, q = e & 63;
        float4 v = __ldg((const float4*)(x + (size_t)(r0 + row) * D_DIM) + q);
        int d = q * 4;
        xs[(d + 0) * SX + row] = v.x;
        xs[(d + 1) * SX + row] = v.y;
        xs[(d + 2) * SX + row] = v.z;
        xs[(d + 3) * SX + row] = v.w;
    }

    float xsqr[8], bestv[8];
    int besti[8];
    #pragma unroll
    for (int r = 0; r < 8; ++r) {
        xsqr[r] = g_xsq[r0 + ty * 8 + r];
        bestv[r] = 3.4e38f;
        besti[r] = 0;
    }
    __syncthreads();

    for (int t = 0; t < K_CODES / 128; ++t) {
        ull acc[8][4];
        #pragma unroll
        for (int r = 0; r < 8; ++r)
            #pragma unroll
            for (int c = 0; c < 4; ++c) acc[r][c] = 0ull;

        for (int ch = 0; ch < 4; ++ch) {
            // load W chunk transposed: ws[d][c] for cols t*128.., d = ch*64..
            #pragma unroll
            for (int i = 0; i < 8; ++i) {
                int e = i * 256 + tid;
                int c = e >> 4, q = e & 15;
                int d = q * 4;
                float4 v = __ldg((const float4*)(w + (size_t)(t * 128 + c) * D_DIM
                                                 + ch * 64) + q);
                ws[(d + 0) * SX + c] = v.x;
                ws[(d + 1) * SX + c] = v.y;
                ws[(d + 2) * SX + c] = v.z;
                ws[(d + 3) * SX + c] = v.w;
            }
            __syncthreads();

            const float* xbase = xs + (ch * 64) * SX + ty * 8;
            const float* wbase = ws + tx * 8;
            #pragma unroll 8
            for (int d = 0; d < 64; ++d) {
                float4 xA = *(const float4*)(xbase + d * SX);
                float4 xB = *(const float4*)(xbase + d * SX + 4);
                ulonglong2 wA = *(const ulonglong2*)(wbase + d * SX);
                ulonglong2 wB = *(const ulonglong2*)(wbase + d * SX + 4);
                float xr[8] = {xA.x, xA.y, xA.z, xA.w, xB.x, xB.y, xB.z, xB.w};
                ull wp[4] = {wA.x, wA.y, wB.x, wB.y};
                #pragma unroll
                for (int r = 0; r < 8; ++r) {
                    ull px = pack2(xr[r], xr[r]);
                    #pragma unroll
                    for (int c = 0; c < 4; ++c)
                        acc[r][c] = fma2(px, wp[c], acc[r][c]);
                }
            }
            __syncthreads();  // before next chunk overwrites ws
        }

        // epilogue: replicate ref's fp32 op sequence; strict-less keeps first index
        int cbase = t * 128 + tx * 8;
        float wsqv[8];
        #pragma unroll
        for (int j = 0; j < 8; ++j) wsqv[j] = __ldg(&g_wsq[cbase + j]);
        #pragma unroll
        for (int r = 0; r < 8; ++r) {
            #pragma unroll
            for (int c = 0; c < 4; ++c) {
                float glo, ghi;
                unpack2(acc[r][c], glo, ghi);
                float d1 = __fsub_rn(xsqr[r], __fmul_rn(2.0f, glo));
                float dv = __fadd_rn(d1, wsqv[2 * c]);
                if (dv < bestv[r]) { bestv[r] = dv; besti[r] = cbase + 2 * c; }
                d1 = __fsub_rn(xsqr[r], __fmul_rn(2.0f, ghi));
                dv = __fadd_rn(d1, wsqv[2 * c + 1]);
                if (dv < bestv[r]) { bestv[r] = dv; besti[r] = cbase + 2 * c + 1; }
            }
        }
    }

    // reduce across the 16 tx lanes (within half-warp), lexicographic (val, idx)
    #pragma unroll
    for (int r = 0; r < 8; ++r) {
        float v = bestv[r];
        int bi = besti[r];
        #pragma unroll
        for (int m = 8; m > 0; m >>= 1) {
            float vo = __shfl_xor_sync(0xffffffffu, v, m);
            int io = __shfl_xor_sync(0xffffffffu, bi, m);
            if (vo < v || (vo == v && io < bi)) { v = vo; bi = io; }
        }
        if (tx == 0) {
            int row = r0 + ty * 8 + r;
            g_idx[row] = bi;
            if (idx_out) idx_out[row] = (float)bi;
        }
    }
}

// gather codewords, write straight-through output, accumulate loss partials
__global__ __launch_bounds__(256)
void loss_gather_kernel(const float* __restrict__ x, const float* __restrict__ w,
                        float* __restrict__ qst)
{
    __shared__ double sred[256];
    int tid = threadIdx.x;
    double s = 0.0;
    size_t base = (size_t)blockIdx.x * 2048;
    #pragma unroll
    for (int i = 0; i < 2; ++i) {
        size_t e = base + (size_t)tid * 4 + (size_t)i * 1024;
        int row = (int)(e >> 8);
        int d = (int)(e & 255);
        int idx = g_idx[row];
        float4 xv = *(const float4*)(x + e);
        float4 qv = __ldg((const float4*)(w + (size_t)idx * D_DIM + d));
        float4 o;
        o.x = __fadd_rn(xv.x, __fsub_rn(qv.x, xv.x));
        o.y = __fadd_rn(xv.y, __fsub_rn(qv.y, xv.y));
        o.z = __fadd_rn(xv.z, __fsub_rn(qv.z, xv.z));
        o.w = __fadd_rn(xv.w, __fsub_rn(qv.w, xv.w));
        *(float4*)(qst + e) = o;
        float dx;
        dx = __fsub_rn(xv.x, qv.x); s += (double)__fmul_rn(dx, dx);
        dx = __fsub_rn(xv.y, qv.y); s += (double)__fmul_rn(dx, dx);
        dx = __fsub_rn(xv.z, qv.z); s += (double)__fmul_rn(dx, dx);
        dx = __fsub_rn(xv.w, qv.w); s += (double)__fmul_rn(dx, dx);
    }
    sred[tid] = s;
    __syncthreads();
    for (int st = 128; st > 0; st >>= 1) {
        if (tid < st) sred[tid] += sred[tid + st];
        __syncthreads();
    }
    if (tid == 0) g_part[blockIdx.x] = sred[0];
}

__global__ __launch_bounds__(256)
void finalize_kernel(float* __restrict__ sc)
{
    __shared__ double sred[256];
    int tid = threadIdx.x;
    double s = 0.0;
    for (int j = tid; j < 4096; j += 256) s += g_part[j];
    sred[tid] = s;
    __syncthreads();
    for (int st = 128; st > 0; st >>= 1) {
        if (tid < st) sred[tid] += sred[tid + st];
        __syncthreads();
    }
    if (tid == 0 && sc) {
        double mean = sred[0] / (double)((size_t)N_ROWS * D_DIM);
        float M = (float)mean;
        float commit = __fmul_rn(M, 0.25f);
        sc[0] = commit;                 // commitment_loss
        sc[1] = M;                      // codebook_loss
        sc[2] = __fadd_rn(commit, M);   // total
    }
}

extern "C" void kernel_launch(void* const* d_in, const int* in_sizes, int n_in,
                              void* d_out, int out_size)
{
    const float* x = (const float*)d_in[0];
    const float* w = (const float*)d_in[1];
    // defensive: identify x (N*D) vs weight (K*D) by element count
    if (n_in >= 2 && in_sizes[0] == K_CODES * D_DIM && in_sizes[1] == N_ROWS * D_DIM) {
        const float* t = x; x = w; w = t;
    }

    float* out = (float*)d_out;
    const int ND = N_ROWS * D_DIM;
    float* qst = out;
    float* idxo = (out_size >= ND + N_ROWS) ? out + ND : nullptr;
    float* sc = (out_size >= ND + N_ROWS + 3) ? out + ND + N_ROWS : nullptr;

    static int smem_set = 0;
    if (!smem_set) {
        cudaFuncSetAttribute(vq_argmin_kernel,
                             cudaFuncAttributeMaxDynamicSharedMemorySize, SMEM_BYTES);
        smem_set = 1;
    }

    rowsq_kernel<<<K_CODES / 256, 256>>>(w, K_CODES, 0);
    rowsq_kernel<<<N_ROWS / 256, 256>>>(x, N_ROWS, 1);
    vq_argmin_kernel<<<N_ROWS / 128, 256, SMEM_BYTES>>>(x, w, idxo);
    loss_gather_kernel<<<4096, 256>>>(x, w, qst);
    finalize_kernel<<<1, 256>>>(sc);
}

// round 4
// speedup vs baseline: 1.1616x; 1.1605x over previous
#include <cuda_runtime.h>
#include <cuda_bf16.h>
#include <stdint.h>

typedef unsigned long long ull;

#define N_ROWS 32768
#define K_CODES 8192
#define D_DIM 256
#define SPLITS 4
#define KSPLIT (K_CODES / SPLITS)      // 2048
#define RPB 128                        // rows per block
#define COLTILE 256                    // cols per tile iteration
#define NTILES (KSPLIT / COLTILE)      // 8
#define DCHUNK 32
#define NM (NTILES * (D_DIM / DCHUNK)) // 64 chunks per block
#define SXR 260                        // xs row stride (floats)
#define SWP 132                        // ws pair-row stride (ull pairs)
#define SMEM_BYTES (RPB*SXR*4 + 2*DCHUNK*SWP*8)   // 133120 + 67584 = 200704

__device__ float  g_wsq[K_CODES];
__device__ float  g_xsq[N_ROWS];
__device__ int    g_idx[N_ROWS];
__device__ float  g_cand_val[SPLITS * N_ROWS];
__device__ int    g_cand_idx[SPLITS * N_ROWS];
__device__ double g_part[4096];

__device__ __forceinline__ ull fma2(ull a, ull b, ull c) {
    ull d;
    asm("fma.rn.f32x2 %0, %1, %2, %3;" : "=l"(d) : "l"(a), "l"(b), "l"(c));
    return d;
}
__device__ __forceinline__ ull pack2(float a, float b) {
    ull r;
    asm("mov.b64 %0, {%1, %2};" : "=l"(r) : "f"(a), "f"(b));
    return r;
}
__device__ __forceinline__ void unpack2(ull v, float& lo, float& hi) {
    asm("mov.b64 {%0, %1}, %2;" : "=f"(lo), "=f"(hi) : "l"(v));
}
__device__ __forceinline__ void cp16(uint32_t dst, const void* src) {
    asm volatile("cp.async.cg.shared.global [%0], [%1], 16;" :: "r"(dst), "l"(src));
}

// sum of squares per row of [nrows, 256]; any fp32 order is argmin-safe
// (per-row x_sq offset shifts all K distances uniformly; w_sq err ~1e-13)
__global__ __launch_bounds__(256)
void rowsq_kernel(const float* __restrict__ src, int nrows, int which) {
    int row = blockIdx.x * 256 + threadIdx.x;
    if (row >= nrows) return;
    const float4* p = (const float4*)(src + (size_t)row * D_DIM);
    float s0 = 0.f, s1 = 0.f, s2 = 0.f, s3 = 0.f;
    #pragma unroll 8
    for (int c = 0; c < D_DIM / 4; ++c) {
        float4 v = __ldg(p + c);
        s0 = __fmaf_rn(v.x, v.x, s0);
        s1 = __fmaf_rn(v.y, v.y, s1);
        s2 = __fmaf_rn(v.z, v.z, s2);
        s3 = __fmaf_rn(v.w, v.w, s3);
    }
    float r = __fadd_rn(__fadd_rn(s0, s1), __fadd_rn(s2, s3));
    if (which == 0) g_wsq[row] = r; else g_xsq[row] = r;
}

// Fused dist2 argmin. Block: 128 rows x 2048 codes (one K-split).
// Thread tile 8 rows x 16 cols (8 f32x2 pairs). Exact sequential-k fp32
// accumulation per lane; conflict-free smem; double-buffered w chunks.
__global__ __launch_bounds__(256, 1)
void vq_argmin_kernel(const float* __restrict__ x, const float* __restrict__ w)
{
    extern __shared__ float sm[];
    float* xs = sm;                               // [128 rows][260] (16B-XOR swizzled)
    ull* wsp  = (ull*)(sm + RPB * SXR);           // [2][32 d][132 pairs]

    const int tid = threadIdx.x;
    const int tx = tid & 15;                      // pair group
    const int ty = tid >> 4;                      // 8-row group
    const int q  = tid & 127;                     // staging pair id
    const int dh = tid >> 7;                      // staging d-half
    const int r0 = blockIdx.x * RPB;
    const int ksBase = blockIdx.y * KSPLIT;
    const int xoff = (ty & 1) * 4;                // x d-swizzle for this thread

    // ---- xs via cp.async, natural layout + 16B XOR swizzle per 8-row group ----
    #pragma unroll
    for (int i = 0; i < 32; ++i) {
        int e = i * 256 + tid;
        int row = e >> 6, g = e & 63;
        uint32_t dst = (uint32_t)__cvta_generic_to_shared(
            xs + row * SXR + ((g ^ ((row >> 3) & 1)) << 2));
        cp16(dst, x + (size_t)(r0 + row) * D_DIM + g * 4);
    }
    asm volatile("cp.async.commit_group;" ::: "memory");

    float xsqr[8];
    #pragma unroll
    for (int r = 0; r < 8; ++r) xsqr[r] = g_xsq[r0 + ty * 8 + r];

    float bestv[8];
    int besti[8];
    #pragma unroll
    for (int r = 0; r < 8; ++r) { bestv[r] = 3.4e38f; besti[r] = 0; }

    // ---- w chunk staging helpers ----
    float4 st[8];
    auto ldg_chunk = [&](int m) {
        int t = m >> 3, c = m & 7;
        const float* base = w + (size_t)(ksBase + t * COLTILE + 2 * q) * D_DIM
                              + c * DCHUNK + dh * 16;
        const float4* p0 = (const float4*)base;
        const float4* p1 = (const float4*)(base + D_DIM);
        st[0] = __ldg(p0 + 0); st[1] = __ldg(p0 + 1);
        st[2] = __ldg(p0 + 2); st[3] = __ldg(p0 + 3);
        st[4] = __ldg(p1 + 0); st[5] = __ldg(p1 + 1);
        st[6] = __ldg(p1 + 2); st[7] = __ldg(p1 + 3);
    };
    auto sts_chunk = [&](ull* dbuf) {
        #pragma unroll
        for (int k = 0; k < 4; ++k) {
            const float* a = (const float*)&st[k];
            const float* b = (const float*)&st[4 + k];
            #pragma unroll
            for (int e = 0; e < 4; ++e)
                dbuf[(dh * 16 + k * 4 + e) * SWP + q] = pack2(a[e], b[e]);
        }
    };

    // prologue: chunk 0 staged, stored; chunk 1 staged
    ldg_chunk(0);
    asm volatile("cp.async.wait_group 0;" ::: "memory");
    sts_chunk(wsp);
    __syncthreads();
    ldg_chunk(1);

    const float* xrow = xs + (ty * 8) * SXR;

    for (int t = 0; t < NTILES; ++t) {
        ull acc[8][8];
        #pragma unroll
        for (int r = 0; r < 8; ++r)
            #pragma unroll
            for (int j = 0; j < 8; ++j) acc[r][j] = 0ull;

        for (int c = 0; c < D_DIM / DCHUNK; ++c) {
            const int m = t * 8 + c;
            if (m + 1 < NM) sts_chunk(wsp + ((m + 1) & 1) * (DCHUNK * SWP));
            if (m + 2 < NM) ldg_chunk(m + 2);

            const ull* wrow = wsp + (m & 1) * (DCHUNK * SWP) + tx;
            const int dbase = c * DCHUNK;
            #pragma unroll 4
            for (int dl = 0; dl < DCHUNK; ++dl) {
                ull wv[8];
                #pragma unroll
                for (int j = 0; j < 8; ++j) wv[j] = wrow[dl * SWP + 16 * j];
                const float* xp = xrow + ((dbase + dl) ^ xoff);
                ull px[8];
                #pragma unroll
                for (int r = 0; r < 8; ++r) {
                    float xv = xp[r * SXR];
                    px[r] = pack2(xv, xv);
                }
                #pragma unroll
                for (int r = 0; r < 8; ++r)
                    #pragma unroll
                    for (int j = 0; j < 8; ++j)
                        acc[r][j] = fma2(px[r], wv[j], acc[r][j]);
            }
            __syncthreads();
        }

        // epilogue: exact ref op sequence, strict-less = first-index ties
        const int cb = ksBase + t * COLTILE;
        #pragma unroll
        for (int j = 0; j < 8; ++j) {
            int col0 = cb + 2 * (tx + 16 * j);
            float w0 = __ldg(&g_wsq[col0]);
            float w1 = __ldg(&g_wsq[col0 + 1]);
            #pragma unroll
            for (int r = 0; r < 8; ++r) {
                float glo, ghi;
                unpack2(acc[r][j], glo, ghi);
                float dv = __fadd_rn(__fsub_rn(xsqr[r], __fmul_rn(2.0f, glo)), w0);
                if (dv < bestv[r]) { bestv[r] = dv; besti[r] = col0; }
                dv = __fadd_rn(__fsub_rn(xsqr[r], __fmul_rn(2.0f, ghi)), w1);
                if (dv < bestv[r]) { bestv[r] = dv; besti[r] = col0 + 1; }
            }
        }
    }

    // reduce over the 16 tx lanes, lexicographic (val, idx)
    #pragma unroll
    for (int r = 0; r < 8; ++r) {
        float v = bestv[r];
        int bi = besti[r];
        #pragma unroll
        for (int msk = 8; msk > 0; msk >>= 1) {
            float vo = __shfl_xor_sync(0xffffffffu, v, msk);
            int io = __shfl_xor_sync(0xffffffffu, bi, msk);
            if (vo < v || (vo == v && io < bi)) { v = vo; bi = io; }
        }
        if (tx == 0) {
            int slot = blockIdx.y * N_ROWS + r0 + ty * 8 + r;
            g_cand_val[slot] = v;
            g_cand_idx[slot] = bi;
        }
    }
}

// merge the SPLITS candidates per row, ascending K order, strict-less
__global__ __launch_bounds__(256)
void combine_kernel(float* __restrict__ idx_out)
{
    int row = blockIdx.x * 256 + threadIdx.x;
    if (row >= N_ROWS) return;
    float bv = g_cand_val[row];
    int bi = g_cand_idx[row];
    #pragma unroll
    for (int s = 1; s < SPLITS; ++s) {
        float v = g_cand_val[s * N_ROWS + row];
        int i = g_cand_idx[s * N_ROWS + row];
        if (v < bv) { bv = v; bi = i; }
    }
    g_idx[row] = bi;
    if (idx_out) idx_out[row] = (float)bi;
}

// gather codewords, straight-through output, loss partials
__global__ __launch_bounds__(256)
void loss_gather_kernel(const float* __restrict__ x, const float* __restrict__ w,
                        float* __restrict__ qst)
{
    __shared__ double sred[256];
    int tid = threadIdx.x;
    double s = 0.0;
    size_t base = (size_t)blockIdx.x * 2048;
    #pragma unroll
    for (int i = 0; i < 2; ++i) {
        size_t e = base + (size_t)tid * 4 + (size_t)i * 1024;
        int row = (int)(e >> 8);
        int d = (int)(e & 255);
        int idx = g_idx[row];
        float4 xv = *(const float4*)(x + e);
        float4 qv = __ldg((const float4*)(w + (size_t)idx * D_DIM + d));
        float4 o;
        o.x = __fadd_rn(xv.x, __fsub_rn(qv.x, xv.x));
        o.y = __fadd_rn(xv.y, __fsub_rn(qv.y, xv.y));
        o.z = __fadd_rn(xv.z, __fsub_rn(qv.z, xv.z));
        o.w = __fadd_rn(xv.w, __fsub_rn(qv.w, xv.w));
        *(float4*)(qst + e) = o;
        float dx;
        dx = __fsub_rn(xv.x, qv.x); s += (double)__fmul_rn(dx, dx);
        dx = __fsub_rn(xv.y, qv.y); s += (double)__fmul_rn(dx, dx);
        dx = __fsub_rn(xv.z, qv.z); s += (double)__fmul_rn(dx, dx);
        dx = __fsub_rn(xv.w, qv.w); s += (double)__fmul_rn(dx, dx);
    }
    sred[tid] = s;
    __syncthreads();
    for (int st = 128; st > 0; st >>= 1) {
        if (tid < st) sred[tid] += sred[tid + st];
        __syncthreads();
    }
    if (tid == 0) g_part[blockIdx.x] = sred[0];
}

__global__ __launch_bounds__(256)
void finalize_kernel(float* __restrict__ sc)
{
    __shared__ double sred[256];
    int tid = threadIdx.x;
    double s = 0.0;
    for (int j = tid; j < 4096; j += 256) s += g_part[j];
    sred[tid] = s;
    __syncthreads();
    for (int st = 128; st > 0; st >>= 1) {
        if (tid < st) sred[tid] += sred[tid + st];
        __syncthreads();
    }
    if (tid == 0 && sc) {
        double mean = sred[0] / (double)((size_t)N_ROWS * D_DIM);
        float M = (float)mean;
        float commit = __fmul_rn(M, 0.25f);
        sc[0] = commit;
        sc[1] = M;
        sc[2] = __fadd_rn(commit, M);
    }
}

extern "C" void kernel_launch(void* const* d_in, const int* in_sizes, int n_in,
                              void* d_out, int out_size)
{
    const float* x = (const float*)d_in[0];
    const float* w = (const float*)d_in[1];
    if (n_in >= 2 && in_sizes[0] == K_CODES * D_DIM && in_sizes[1] == N_ROWS * D_DIM) {
        const float* t = x; x = w; w = t;
    }

    float* out = (float*)d_out;
    const int ND = N_ROWS * D_DIM;
    float* qst = out;
    float* idxo = (out_size >= ND + N_ROWS) ? out + ND : nullptr;
    float* sc = (out_size >= ND + N_ROWS + 3) ? out + ND + N_ROWS : nullptr;

    static int smem_set = 0;
    if (!smem_set) {
        cudaFuncSetAttribute(vq_argmin_kernel,
                             cudaFuncAttributeMaxDynamicSharedMemorySize, SMEM_BYTES);
        smem_set = 1;
    }

    rowsq_kernel<<<K_CODES / 256, 256>>>(w, K_CODES, 0);
    rowsq_kernel<<<N_ROWS / 256, 256>>>(x, N_ROWS, 1);
    vq_argmin_kernel<<<dim3(N_ROWS / RPB, SPLITS), 256, SMEM_BYTES>>>(x, w);
    combine_kernel<<<N_ROWS / 256, 256>>>(idxo);
    loss_gather_kernel<<<4096, 256>>>(x, w, qst);
    finalize_kernel<<<1, 256>>>(sc);
}